// round 5
// baseline (speedup 1.0000x reference)
#include <cuda_runtime.h>
#include <math.h>

#define N_NODES 100000
#define N_EDGES 6400000
#define F_IN    128
#define F_OUT   16

// ------------- device scratch (zero-initialized; invariants restored) -----
__device__ int   g_deg [N_NODES];            // in-deg; gemm resets to 0
__device__ float g_dinv[N_NODES];            // rsqrt(deg+1), written by gemm
__device__ float g_g   [N_NODES * F_OUT];    // dinv[n] * (x[n] @ W)
__device__ float g_acc [N_NODES * F_OUT];    // scatter acc; finalize resets

// K1: in-degree of target nodes (proven ~25us, REDG floor)
__global__ void __launch_bounds__(256) k_degree(const int* __restrict__ dst) {
    int e = blockIdx.x * 256 + threadIdx.x;
    if (e < N_EDGES) atomicAdd(&g_deg[dst[e]], 1);
}

// K2: g[n] = rsqrt(deg[n]+1) * (x[n] @ W); 2 threads per node (K-split).
// Also: stores dinv, resets deg, zeroes out.
__global__ void __launch_bounds__(256) k_gemm(const float* __restrict__ x,
                                              const float* __restrict__ W,
                                              float* __restrict__ out) {
    __shared__ float Ws[F_IN * F_OUT];
    for (int i = threadIdx.x; i < F_IN * F_OUT; i += 256) Ws[i] = W[i];
    __syncthreads();

    int gt = blockIdx.x * 256 + threadIdx.x;
    if (gt < F_OUT) out[gt] = 0.0f;            // zero output accumulator
    int n = gt >> 1;                            // node
    int part = gt & 1;                          // K half: 64 floats
    if (n >= N_NODES) return;

    const float4* x4 = (const float4*)(x + (size_t)n * F_IN) + part * 16;
    float acc[F_OUT];
#pragma unroll
    for (int f = 0; f < F_OUT; f++) acc[f] = 0.f;

#pragma unroll
    for (int k4 = 0; k4 < 16; k4++) {
        float4 xv = x4[k4];
        int k = part * 64 + k4 * 4;
#pragma unroll
        for (int f = 0; f < F_OUT; f++) {
            acc[f] += xv.x * Ws[(k + 0) * F_OUT + f];
            acc[f] += xv.y * Ws[(k + 1) * F_OUT + f];
            acc[f] += xv.z * Ws[(k + 2) * F_OUT + f];
            acc[f] += xv.w * Ws[(k + 3) * F_OUT + f];
        }
    }
    // combine the 2 K-halves (partner lane differs in bit 0)
#pragma unroll
    for (int f = 0; f < F_OUT; f++)
        acc[f] += __shfl_xor_sync(0xFFFFFFFFu, acc[f], 1);

    if (part == 0) {
        float dv = rsqrtf((float)(g_deg[n] + 1));  // +1 self loop
        g_dinv[n] = dv;
        g_deg[n] = 0;                              // restore for next replay
        float4* gg = (float4*)(g_g + (size_t)n * F_OUT);
#pragma unroll
        for (int q = 0; q < 4; q++)
            gg[q] = make_float4(acc[q * 4 + 0] * dv, acc[q * 4 + 1] * dv,
                                acc[q * 4 + 2] * dv, acc[q * 4 + 3] * dv);
    }
}

// K3: acc[dst] += g[src]  (4 threads/edge, vector RED) — proven, at REDG floor
__global__ void __launch_bounds__(256) k_scatter(const int* __restrict__ src,
                                                 const int* __restrict__ dst) {
    long long t = (long long)blockIdx.x * 256 + threadIdx.x;
    int e = (int)(t >> 2);
    int q = (int)(t & 3);
    if (e >= N_EDGES) return;
    int r = src[e];
    int c = dst[e];
    float4 v = ((const float4*)g_g)[r * 4 + q];
    float* p = g_acc + (size_t)c * F_OUT + q * 4;
    asm volatile("red.global.add.v4.f32 [%0], {%1,%2,%3,%4};"
                 :: "l"(p), "f"(v.x), "f"(v.y), "f"(v.z), "f"(v.w)
                 : "memory");
}

// K4: out = mean_n tanh(dinv*(acc+g) + b); 2 threads/node; resets acc.
__global__ void __launch_bounds__(256) k_finalize(const float* __restrict__ b,
                                                  float* __restrict__ out) {
    int t = blockIdx.x * 256 + threadIdx.x;
    int lane = threadIdx.x & 31;
    int n = t >> 1;                            // node
    int h = t & 1;                             // feature half: 8 floats

    float local[8];
#pragma unroll
    for (int j = 0; j < 8; j++) local[j] = 0.f;

    if (n < N_NODES) {
        float dv = g_dinv[n];
        float4* a4 = (float4*)(g_acc + (size_t)n * F_OUT) + h * 2;
        const float4* g4 = (const float4*)(g_g + (size_t)n * F_OUT) + h * 2;
        const float4* b4 = (const float4*)b + h * 2;
        const float4 z4 = make_float4(0.f, 0.f, 0.f, 0.f);
#pragma unroll
        for (int q = 0; q < 2; q++) {
            float4 a = a4[q];
            float4 g = g4[q];
            float4 bb = b4[q];
            a4[q] = z4;                        // restore acc for next replay
            local[q * 4 + 0] = tanhf(dv * (a.x + g.x) + bb.x);
            local[q * 4 + 1] = tanhf(dv * (a.y + g.y) + bb.y);
            local[q * 4 + 2] = tanhf(dv * (a.z + g.z) + bb.z);
            local[q * 4 + 3] = tanhf(dv * (a.w + g.w) + bb.w);
        }
    }

    // reduce over the 16 same-parity lanes (offsets 2,4,8,16)
#pragma unroll
    for (int off = 2; off < 32; off <<= 1) {
#pragma unroll
        for (int j = 0; j < 8; j++)
            local[j] += __shfl_xor_sync(0xFFFFFFFFu, local[j], off);
    }
    if (lane < 2) {                            // lane0: f0-7, lane1: f8-15
#pragma unroll
        for (int j = 0; j < 8; j++)
            atomicAdd(&out[lane * 8 + j], local[j] * (1.0f / (float)N_NODES));
    }
}

// ---------------- launch ---------------------------------------------------
extern "C" void kernel_launch(void* const* d_in, const int* in_sizes, int n_in,
                              void* d_out, int out_size) {
    const float* x  = (const float*)d_in[0];
    const int*   ei = (const int*)d_in[1];   // [2, N_EDGES] int32 (JAX x64 off)
    const float* W  = (const float*)d_in[2];
    const float* b  = (const float*)d_in[3];
    float*       out = (float*)d_out;

    const int* src = ei;
    const int* dst = ei + N_EDGES;

    k_degree<<<(N_EDGES + 255) / 256, 256>>>(dst);
    k_gemm  <<<(2 * N_NODES + 255) / 256, 256>>>(x, W, out);
    {
        long long threads = (long long)N_EDGES * 4;
        k_scatter<<<(int)((threads + 255) / 256), 256>>>(src, dst);
    }
    k_finalize<<<(2 * N_NODES + 255) / 256, 256>>>(b, out);
}

// round 6
// speedup vs baseline: 1.2304x; 1.2304x over previous
#include <cuda_runtime.h>
#include <math.h>

#define N_NODES 100000
#define N_EDGES 6400000
#define F_IN    128
#define F_OUT   16

// ------------- device scratch (zero-initialized; invariants restored) -----
__device__ int   g_deg [N_NODES];            // in-deg; k_dinv resets to 0
__device__ float g_dinv[N_NODES];            // rsqrt(deg+1)
__device__ float g_g   [N_NODES * F_OUT];    // h = x@W, then scaled by dinv
__device__ float g_acc [N_NODES * F_OUT];    // scatter acc; finalize resets

// K-deg: in-degree of target nodes (R2-proven shape)
__global__ void __launch_bounds__(256) k_degree(const int* __restrict__ dst) {
    int e = blockIdx.x * 256 + threadIdx.x;
    if (e < N_EDGES) atomicAdd(&g_deg[dst[e]], 1);
}

// K-gemm: h[n] = x[n] @ W  (independent of degrees!)  1 thread per node,
// 128-thread blocks — the R2/R3-proven shape.
__global__ void __launch_bounds__(128) k_gemm_h(const float* __restrict__ x,
                                                const float* __restrict__ W) {
    __shared__ float Ws[F_IN * F_OUT];
    for (int i = threadIdx.x; i < F_IN * F_OUT; i += 128) Ws[i] = W[i];
    __syncthreads();

    int n = blockIdx.x * 128 + threadIdx.x;
    if (n >= N_NODES) return;

    const float4* x4 = (const float4*)(x + (size_t)n * F_IN);
    float acc[F_OUT];
#pragma unroll
    for (int f = 0; f < F_OUT; f++) acc[f] = 0.f;

#pragma unroll
    for (int k4 = 0; k4 < F_IN / 4; k4++) {
        float4 xv = x4[k4];
        int k = k4 * 4;
#pragma unroll
        for (int f = 0; f < F_OUT; f++) {
            acc[f] += xv.x * Ws[(k + 0) * F_OUT + f];
            acc[f] += xv.y * Ws[(k + 1) * F_OUT + f];
            acc[f] += xv.z * Ws[(k + 2) * F_OUT + f];
            acc[f] += xv.w * Ws[(k + 3) * F_OUT + f];
        }
    }
    float4* gg = (float4*)(g_g + (size_t)n * F_OUT);
#pragma unroll
    for (int q = 0; q < 4; q++)
        gg[q] = make_float4(acc[q * 4 + 0], acc[q * 4 + 1],
                            acc[q * 4 + 2], acc[q * 4 + 3]);
}

// K-dinv: dinv = rsqrt(deg+1); g *= dinv; reset deg; zero out. (R4-proven)
__global__ void __launch_bounds__(256) k_dinv(float* __restrict__ out) {
    int n = blockIdx.x * 256 + threadIdx.x;
    if (n < N_NODES) {
        float dv = rsqrtf((float)(g_deg[n] + 1));
        g_dinv[n] = dv;
        g_deg[n] = 0;                          // restore invariant for replay
        float4* gg = (float4*)(g_g + (size_t)n * F_OUT);
#pragma unroll
        for (int q = 0; q < 4; q++) {
            float4 v = gg[q];
            gg[q] = make_float4(v.x * dv, v.y * dv, v.z * dv, v.w * dv);
        }
    }
    if (n < F_OUT) out[n] = 0.0f;
}

// K-scatter: acc[dst] += g[src]  (4 threads/edge, vector RED) — R2-proven
__global__ void __launch_bounds__(256) k_scatter(const int* __restrict__ src,
                                                 const int* __restrict__ dst) {
    long long t = (long long)blockIdx.x * 256 + threadIdx.x;
    int e = (int)(t >> 2);
    int q = (int)(t & 3);
    if (e >= N_EDGES) return;
    int r = src[e];
    int c = dst[e];
    float4 v = ((const float4*)g_g)[r * 4 + q];
    float* p = g_acc + (size_t)c * F_OUT + q * 4;
    asm volatile("red.global.add.v4.f32 [%0], {%1,%2,%3,%4};"
                 :: "l"(p), "f"(v.x), "f"(v.y), "f"(v.z), "f"(v.w)
                 : "memory");
}

// K-fin: out = mean_n tanh(dinv*(acc+g) + b); resets acc. (R4-proven, 20.5us)
__global__ void __launch_bounds__(256) k_finalize(const float* __restrict__ b,
                                                  float* __restrict__ out) {
    float bb[F_OUT];
#pragma unroll
    for (int f = 0; f < F_OUT; f++) bb[f] = b[f];

    float local[F_OUT];
#pragma unroll
    for (int f = 0; f < F_OUT; f++) local[f] = 0.f;

    const float4 z4 = make_float4(0.f, 0.f, 0.f, 0.f);
    for (int n = blockIdx.x * 256 + threadIdx.x; n < N_NODES;
         n += gridDim.x * 256) {
        float dv = g_dinv[n];
        float4* a4 = (float4*)(g_acc + (size_t)n * F_OUT);
        const float4* g4 = (const float4*)(g_g + (size_t)n * F_OUT);
#pragma unroll
        for (int q = 0; q < 4; q++) {
            float4 a = a4[q];
            float4 g = g4[q];
            a4[q] = z4;                        // restore invariant for replay
            local[q * 4 + 0] += tanhf(dv * (a.x + g.x) + bb[q * 4 + 0]);
            local[q * 4 + 1] += tanhf(dv * (a.y + g.y) + bb[q * 4 + 1]);
            local[q * 4 + 2] += tanhf(dv * (a.z + g.z) + bb[q * 4 + 2]);
            local[q * 4 + 3] += tanhf(dv * (a.w + g.w) + bb[q * 4 + 3]);
        }
    }

#pragma unroll
    for (int off = 16; off > 0; off >>= 1) {
#pragma unroll
        for (int f = 0; f < F_OUT; f++)
            local[f] += __shfl_xor_sync(0xFFFFFFFFu, local[f], off);
    }
    if ((threadIdx.x & 31) < F_OUT) {
        atomicAdd(&out[threadIdx.x & 31],
                  local[threadIdx.x & 31] * (1.0f / (float)N_NODES));
    }
}

// ---------------- launch: fork degree onto a side stream -------------------
extern "C" void kernel_launch(void* const* d_in, const int* in_sizes, int n_in,
                              void* d_out, int out_size) {
    const float* x  = (const float*)d_in[0];
    const int*   ei = (const int*)d_in[1];   // [2, N_EDGES] int32 (JAX x64 off)
    const float* W  = (const float*)d_in[2];
    const float* b  = (const float*)d_in[3];
    float*       out = (float*)d_out;

    const int* src = ei;
    const int* dst = ei + N_EDGES;

    // Fork-join so k_degree (L2/atomic-bound) overlaps k_gemm_h (DRAM-bound).
    // Created fresh each call (no static guards); intentionally not destroyed
    // (capture may still be active when we return; a handful of leaked
    // streams/events across the harness's few calls is harmless and is not
    // device-memory allocation).
    cudaStream_t s2;
    cudaEvent_t eFork, eJoin;
    cudaStreamCreateWithFlags(&s2, cudaStreamNonBlocking);
    cudaEventCreateWithFlags(&eFork, cudaEventDisableTiming);
    cudaEventCreateWithFlags(&eJoin, cudaEventDisableTiming);

    cudaEventRecord(eFork, 0);                 // origin (possibly capturing)
    cudaStreamWaitEvent(s2, eFork, 0);         // s2 joins the capture

    k_degree<<<(N_EDGES + 255) / 256, 256, 0, s2>>>(dst);
    cudaEventRecord(eJoin, s2);

    k_gemm_h<<<(N_NODES + 127) / 128, 128>>>(x, W);   // concurrent with degree

    cudaStreamWaitEvent(0, eJoin, 0);          // join back to origin stream

    k_dinv<<<(N_NODES + 255) / 256, 256>>>(out);
    {
        long long threads = (long long)N_EDGES * 4;
        k_scatter<<<(int)((threads + 255) / 256), 256>>>(src, dst);
    }
    k_finalize<<<592, 256>>>(b, out);
}

// round 7
// speedup vs baseline: 1.4468x; 1.1759x over previous
#include <cuda_runtime.h>
#include <math.h>

#define N_NODES 100000
#define N_EDGES 6400000
#define F_IN    128
#define F_OUT   16

// ---------------- device scratch (no allocations allowed) ----------------
__device__ float g_deg[N_NODES];                 // degree incl. self loop
__device__ float g_g  [N_NODES * F_OUT];         // dinv[n] * (x[n] @ W)
__device__ float g_acc[N_NODES * F_OUT];         // scatter accumulator

// ---------------- K0: reset all state (runs every call / replay) ----------
__global__ void __launch_bounds__(256) k_init(float* __restrict__ out) {
    int i = blockIdx.x * blockDim.x + threadIdx.x;
    int total4 = N_NODES * F_OUT / 4;            // 400000 float4 of acc
    if (i < total4) ((float4*)g_acc)[i] = make_float4(0.f, 0.f, 0.f, 0.f);
    if (i < N_NODES) g_deg[i] = 1.0f;            // self-loop contributes 1
    if (i < F_OUT) out[i] = 0.0f;
}

// ---------------- K1: degree of target nodes ------------------------------
__global__ void __launch_bounds__(256) k_degree(const int* __restrict__ dst) {
    int e = blockIdx.x * blockDim.x + threadIdx.x;
    if (e < N_EDGES) {
        atomicAdd(&g_deg[dst[e]], 1.0f);
    }
}

// ---------------- K2: g[n] = rsqrt(deg[n]) * (x[n] @ W) -------------------
// Coalesced smem staging: 128-thread block stages 128 node rows with flat
// warp-contiguous float4 loads (4 wavefronts/LDG vs 32 for row-per-thread),
// then each thread computes one node from smem (rows padded to 132 floats).
#define GEMM_TPB   128
#define GEMM_NODES 128
#define ROW_PAD    132   // 132*4B = 528B rows, 16B-aligned, 4-way LDS max

__global__ void __launch_bounds__(GEMM_TPB) k_gemm(const float* __restrict__ x,
                                                   const float* __restrict__ W) {
    extern __shared__ float sm[];
    float* sx = sm;                                // [GEMM_NODES][ROW_PAD]
    float* sw = sm + GEMM_NODES * ROW_PAD;         // [F_IN*F_OUT]

    // stage W (coalesced)
    for (int i = threadIdx.x; i < F_IN * F_OUT / 4; i += GEMM_TPB)
        ((float4*)sw)[i] = ((const float4*)W)[i];

    // stage x tile (flat coalesced: consecutive lanes -> consecutive float4)
    int base = blockIdx.x * GEMM_NODES;
    int tile_f4 = min(GEMM_NODES, N_NODES - base) * (F_IN / 4);
    const float4* xg = (const float4*)(x + (size_t)base * F_IN);
    for (int i = threadIdx.x; i < tile_f4; i += GEMM_TPB) {
        float4 v = xg[i];
        int row = i >> 5;                          // 32 float4 per row
        int c4  = i & 31;
        *(float4*)(sx + row * ROW_PAD + c4 * 4) = v;
    }
    __syncthreads();

    int t = threadIdx.x;
    int n = base + t;
    if (n >= N_NODES) return;

    const float4* xr = (const float4*)(sx + t * ROW_PAD);
    float acc[F_OUT];
#pragma unroll
    for (int f = 0; f < F_OUT; f++) acc[f] = 0.f;

#pragma unroll
    for (int k4 = 0; k4 < F_IN / 4; k4++) {
        float4 xv = xr[k4];
        int k = k4 * 4;
#pragma unroll
        for (int f = 0; f < F_OUT; f++) {
            acc[f] += xv.x * sw[(k + 0) * F_OUT + f];
            acc[f] += xv.y * sw[(k + 1) * F_OUT + f];
            acc[f] += xv.z * sw[(k + 2) * F_OUT + f];
            acc[f] += xv.w * sw[(k + 3) * F_OUT + f];
        }
    }
    float dinv = rsqrtf(g_deg[n]);
    float4* gg = (float4*)(g_g + (size_t)n * F_OUT);
#pragma unroll
    for (int q = 0; q < 4; q++) {
        gg[q] = make_float4(acc[q * 4 + 0] * dinv, acc[q * 4 + 1] * dinv,
                            acc[q * 4 + 2] * dinv, acc[q * 4 + 3] * dinv);
    }
}

#define GEMM_SMEM ((GEMM_NODES * ROW_PAD + F_IN * F_OUT) * (int)sizeof(float))

// ---------------- K3: scatter g[src] into acc[dst] (4 threads / edge) -----
__global__ void __launch_bounds__(256) k_scatter(const int* __restrict__ src,
                                                 const int* __restrict__ dst) {
    long long t = (long long)blockIdx.x * blockDim.x + threadIdx.x;
    int e = (int)(t >> 2);
    int q = (int)(t & 3);
    if (e >= N_EDGES) return;
    int r = src[e];
    int c = dst[e];
    float4 v = ((const float4*)g_g)[r * 4 + q];
    float* p = g_acc + (size_t)c * F_OUT + q * 4;
    asm volatile("red.global.add.v4.f32 [%0], {%1,%2,%3,%4};"
                 :: "l"(p), "f"(v.x), "f"(v.y), "f"(v.z), "f"(v.w)
                 : "memory");
}

// ---------------- K4: out = mean_n tanh(dinv*(acc+g) + b) -----------------
__global__ void __launch_bounds__(256) k_finalize(const float* __restrict__ b,
                                                  float* __restrict__ out) {
    float bb[F_OUT];
#pragma unroll
    for (int f = 0; f < F_OUT; f++) bb[f] = b[f];

    float local[F_OUT];
#pragma unroll
    for (int f = 0; f < F_OUT; f++) local[f] = 0.f;

    const float invN = 1.0f / (float)N_NODES;
    for (int n = blockIdx.x * blockDim.x + threadIdx.x; n < N_NODES;
         n += gridDim.x * blockDim.x) {
        float dinv = rsqrtf(g_deg[n]);
        const float4* a4 = (const float4*)(g_acc + (size_t)n * F_OUT);
        const float4* g4 = (const float4*)(g_g + (size_t)n * F_OUT);
#pragma unroll
        for (int q = 0; q < 4; q++) {
            float4 a = a4[q];
            float4 g = g4[q];
            local[q * 4 + 0] += tanhf(dinv * (a.x + g.x) + bb[q * 4 + 0]);
            local[q * 4 + 1] += tanhf(dinv * (a.y + g.y) + bb[q * 4 + 1]);
            local[q * 4 + 2] += tanhf(dinv * (a.z + g.z) + bb[q * 4 + 2]);
            local[q * 4 + 3] += tanhf(dinv * (a.w + g.w) + bb[q * 4 + 3]);
        }
    }

#pragma unroll
    for (int off = 16; off > 0; off >>= 1) {
#pragma unroll
        for (int f = 0; f < F_OUT; f++)
            local[f] += __shfl_xor_sync(0xFFFFFFFFu, local[f], off);
    }
    int lane = threadIdx.x & 31;
    if (lane < F_OUT) {
        atomicAdd(&out[lane], local[lane] * invN);
    }
}

// ---------------- launch ---------------------------------------------------
extern "C" void kernel_launch(void* const* d_in, const int* in_sizes, int n_in,
                              void* d_out, int out_size) {
    const float* x  = (const float*)d_in[0];
    const int*   ei = (const int*)d_in[1];   // [2, N_EDGES] int32 (JAX x64 off)
    const float* W  = (const float*)d_in[2];
    const float* b  = (const float*)d_in[3];
    float*       out = (float*)d_out;

    const int* src = ei;              // edge_index[0]
    const int* dst = ei + N_EDGES;    // edge_index[1]

    // opt-in to >48KB dynamic smem for the staged gemm (not an allocation;
    // attribute set is idempotent and capture-legal)
    cudaFuncSetAttribute(k_gemm, cudaFuncAttributeMaxDynamicSharedMemorySize,
                         GEMM_SMEM);

    {   // K0: reset
        int total = N_NODES * F_OUT / 4;    // 400000 covers all resets
        k_init<<<(total + 255) / 256, 256>>>(out);
    }
    {   // K1: degrees
        k_degree<<<(N_EDGES + 255) / 256, 256>>>(dst);
    }
    {   // K2: staged gemm + dinv scale
        int blocks = (N_NODES + GEMM_NODES - 1) / GEMM_NODES;
        k_gemm<<<blocks, GEMM_TPB, GEMM_SMEM>>>(x, W);
    }
    {   // K3: scatter (4 threads per edge)
        long long threads = (long long)N_EDGES * 4;
        int blocks = (int)((threads + 255) / 256);
        k_scatter<<<blocks, 256>>>(src, dst);
    }
    {   // K4: finalize + mean pool
        k_finalize<<<592, 256>>>(b, out);
    }
}